// round 1
// baseline (speedup 1.0000x reference)
#include <cuda_runtime.h>
#include <math.h>

#define B_    8
#define N_    4096
#define CIN_  64
#define COUT_ 128
#define R_    32
#define R3_   32768
#define NG_   8
#define GN_EPS_ 1e-5f

// ---------------- scratch (static device globals; no allocation) -------------
static __device__ float g_grid[B_ * CIN_ * R3_];      //  64 MB voxel grid
static __device__ float g_cnt [B_ * R3_];             //   1 MB voxel counts
static __device__ int   g_vox [B_ * N_];              //  voxel flat index per point
static __device__ float g_nc  [B_ * N_ * 3];          //  normalized coords
static __device__ float g_h1  [B_ * COUT_ * R3_];     // 128 MB
static __device__ float g_h2  [B_ * COUT_ * R3_];     // 128 MB
static __device__ float g_pf  [B_ * COUT_ * N_];      //  16 MB point branch
static __device__ float g_mean[B_ * NG_];
static __device__ float g_rstd[B_ * NG_];

// ---------------- zero voxel grid + counts ----------------------------------
__global__ void zero_kernel(float* __restrict__ grid, float* __restrict__ cnt) {
    int stride = gridDim.x * blockDim.x;
    int t0 = blockIdx.x * blockDim.x + threadIdx.x;
    for (int i = t0; i < B_ * CIN_ * R3_; i += stride) grid[i] = 0.f;
    for (int i = t0; i < B_ * R3_; i += stride) cnt[i] = 0.f;
}

// ---------------- per-batch coord normalization + voxel index + counts ------
__global__ void coords_kernel(const float* __restrict__ coords,
                              float* __restrict__ nc, int* __restrict__ vox,
                              float* __restrict__ cnt) {
    int b = blockIdx.x, tid = threadIdx.x;
    __shared__ float red[256];
    __shared__ float smean[3];
    __shared__ float sinv;

    float s0 = 0.f, s1 = 0.f, s2 = 0.f;
    for (int n = tid; n < N_; n += 256) {
        const float* c = &coords[(b * N_ + n) * 3];
        s0 += c[0]; s1 += c[1]; s2 += c[2];
    }
    float ss[3] = {s0, s1, s2};
    for (int d = 0; d < 3; d++) {
        red[tid] = ss[d]; __syncthreads();
        for (int st = 128; st > 0; st >>= 1) {
            if (tid < st) red[tid] += red[tid + st];
            __syncthreads();
        }
        if (tid == 0) smean[d] = red[0] * (1.0f / N_);
        __syncthreads();
    }
    float m0 = smean[0], m1 = smean[1], m2 = smean[2];

    float mx = 0.f;
    for (int n = tid; n < N_; n += 256) {
        const float* c = &coords[(b * N_ + n) * 3];
        float dx = c[0] - m0, dy = c[1] - m1, dz = c[2] - m2;
        mx = fmaxf(mx, dx * dx + dy * dy + dz * dz);
    }
    red[tid] = mx; __syncthreads();
    for (int st = 128; st > 0; st >>= 1) {
        if (tid < st) red[tid] = fmaxf(red[tid], red[tid + st]);
        __syncthreads();
    }
    if (tid == 0) sinv = 1.0f / (2.0f * sqrtf(red[0]));
    __syncthreads();
    float inv = sinv;

    for (int n = tid; n < N_; n += 256) {
        const float* c = &coords[(b * N_ + n) * 3];
        float v[3]; int iv[3];
        float cc[3] = {c[0] - m0, c[1] - m1, c[2] - m2};
        #pragma unroll
        for (int d = 0; d < 3; d++) {
            float x = (cc[d] * inv + 0.5f) * (float)R_;
            x = fminf(fmaxf(x, 0.f), (float)(R_ - 1));
            v[d] = x;
            iv[d] = (int)rintf(x);
        }
        nc[(b * N_ + n) * 3 + 0] = v[0];
        nc[(b * N_ + n) * 3 + 1] = v[1];
        nc[(b * N_ + n) * 3 + 2] = v[2];
        int flat = (iv[0] * R_ + iv[1]) * R_ + iv[2];
        vox[b * N_ + n] = flat;
        atomicAdd(&cnt[b * R3_ + flat], 1.0f);
    }
}

// ---------------- scatter features into voxel grid --------------------------
__global__ void scatter_kernel(const float* __restrict__ f,
                               const int* __restrict__ vox,
                               float* __restrict__ grid) {
    int t = blockIdx.x * blockDim.x + threadIdx.x;   // over B*CIN*N
    int n = t & (N_ - 1);
    int bc = t >> 12;            // b*CIN + c
    int b = bc >> 6;             // CIN=64
    int flat = vox[b * N_ + n];
    atomicAdd(&grid[bc * R3_ + flat], f[t]);
}

// ---------------- grid /= max(count,1) --------------------------------------
__global__ void normgrid_kernel(float* __restrict__ grid, const float* __restrict__ cnt) {
    int t = blockIdx.x * blockDim.x + threadIdx.x;   // over B*CIN*R3
    int v = t & (R3_ - 1);
    int b = t >> 21;             // / (CIN*R3) = / (64*32768)
    float c = cnt[b * R3_ + v];
    grid[t] = grid[t] / fmaxf(c, 1.0f);
}

// ---------------- 3x3x3 conv, smem-tiled, z-line in registers ---------------
// block: 256 thr = 16 co x (4x4 xy); each thread computes full z-line (32 acc)
__global__ __launch_bounds__(256, 3)
void conv3d_kernel(const float* __restrict__ in, const float* __restrict__ w,
                   const float* __restrict__ bias, float* __restrict__ out, int Cin) {
    const int CCH = 4;
    __shared__ float sIn[CCH * 6 * 6 * 35];   // z stride 35 -> conflict-free
    __shared__ float sW[16 * CCH * 27];

    int tid = threadIdx.x;
    int tile = blockIdx.x;
    int co0 = blockIdx.y * 16;
    int b = blockIdx.z;
    int x0 = (tile >> 3) * 4, y0 = (tile & 7) * 4;
    int coL = tid >> 4;
    int co = co0 + coL;
    int lx = (tid & 15) >> 2, ly = tid & 3;

    float acc[32];
    float bv = bias[co];
    #pragma unroll
    for (int z = 0; z < 32; z++) acc[z] = bv;

    for (int c0 = 0; c0 < Cin; c0 += CCH) {
        // stage input tile (with halo, zero padded)
        for (int t = tid; t < CCH * 6 * 6 * 34; t += 256) {
            int zz = t % 34;
            int r = t / 34;
            int yy = r % 6; r /= 6;
            int xx = r % 6;
            int ci = r / 6;
            int gx = x0 - 1 + xx, gy = y0 - 1 + yy, gz = zz - 1;
            float v = 0.f;
            if ((unsigned)gx < 32u && (unsigned)gy < 32u && (unsigned)gz < 32u)
                v = in[(((b * Cin + c0 + ci) * 32 + gx) * 32 + gy) * 32 + gz];
            sIn[((ci * 6 + xx) * 6 + yy) * 35 + zz] = v;
        }
        // stage weights
        for (int t = tid; t < 16 * CCH * 27; t += 256) {
            int tap = t % 27;
            int r = t / 27;
            int ci = r % CCH;
            int cl = r / CCH;
            sW[t] = w[((co0 + cl) * Cin + c0 + ci) * 27 + tap];
        }
        __syncthreads();

        for (int ci = 0; ci < CCH; ci++) {
            for (int kx = 0; kx < 3; kx++) {
                for (int ky = 0; ky < 3; ky++) {
                    const float* line = &sIn[((ci * 6 + lx + kx) * 6 + (ly + ky)) * 35];
                    const float* wp = &sW[(coL * CCH + ci) * 27 + (kx * 3 + ky) * 3];
                    float w0 = wp[0], w1 = wp[1], w2 = wp[2];
                    float a = line[0], bb = line[1];
                    #pragma unroll
                    for (int z = 0; z < 32; z++) {
                        float cc = line[z + 2];
                        acc[z] += w0 * a + w1 * bb + w2 * cc;
                        a = bb; bb = cc;
                    }
                }
            }
        }
        __syncthreads();
    }

    float* op = &out[(((b * COUT_ + co) * 32 + (x0 + lx)) * 32 + (y0 + ly)) * 32];
    #pragma unroll
    for (int z = 0; z < 32; z++) op[z] = acc[z];
}

// ---------------- GroupNorm stats: one block per (b, group) -----------------
__global__ void gn_stats_kernel(const float* __restrict__ x, int S,
                                float* __restrict__ mean, float* __restrict__ rstd) {
    int bg = blockIdx.x;                       // b*8 + g ; group = 16 contiguous ch
    const float* p = x + (long)bg * 16 * S;
    int n = 16 * S;
    float s = 0.f, s2 = 0.f;
    for (int i = threadIdx.x; i < n; i += blockDim.x) {
        float v = p[i];
        s += v; s2 += v * v;
    }
    __shared__ float ra[512], rb[512];
    int tid = threadIdx.x;
    ra[tid] = s; rb[tid] = s2; __syncthreads();
    for (int st = 256; st > 0; st >>= 1) {
        if (tid < st) { ra[tid] += ra[tid + st]; rb[tid] += rb[tid + st]; }
        __syncthreads();
    }
    if (tid == 0) {
        float m = ra[0] / (float)n;
        float var = rb[0] / (float)n - m * m;
        mean[bg] = m;
        rstd[bg] = rsqrtf(var + GN_EPS_);
    }
}

// ---------------- GroupNorm apply + swish (in place) ------------------------
__global__ void gn_apply_kernel(float* __restrict__ x, const float* __restrict__ gamma,
                                const float* __restrict__ beta,
                                const float* __restrict__ mean, const float* __restrict__ rstd,
                                int S) {
    int t = blockIdx.x * blockDim.x + threadIdx.x;   // over B*COUT*S
    int c = (t / S) % COUT_;
    int b = t / (S * COUT_);
    int idx = b * NG_ + (c >> 4);
    float y = (x[t] - mean[idx]) * rstd[idx] * gamma[c] + beta[c];
    x[t] = y / (1.0f + expf(-y));
}

// ---------------- point branch GEMM: pf = pt_w @ features + b ---------------
__global__ void ptgemm_kernel(const float* __restrict__ f, const float* __restrict__ w,
                              const float* __restrict__ bias, float* __restrict__ pf) {
    int t = blockIdx.x * blockDim.x + threadIdx.x;   // over B*(COUT/4)*N
    int n = t & (N_ - 1);
    int r = t >> 12;
    int o = (r & 31) * 4;        // COUT/4 = 32
    int b = r >> 5;
    float a0 = bias[o], a1 = bias[o + 1], a2 = bias[o + 2], a3 = bias[o + 3];
    const float* fb = f + (b * CIN_) * N_ + n;
    const float* w0 = w + o * CIN_;
    #pragma unroll 8
    for (int c = 0; c < CIN_; c++) {
        float fv = fb[c * N_];
        a0 += w0[c] * fv;
        a1 += w0[CIN_ + c] * fv;
        a2 += w0[2 * CIN_ + c] * fv;
        a3 += w0[3 * CIN_ + c] * fv;
    }
    float* op = &pf[(b * COUT_ + o) * N_ + n];
    op[0] = a0; op[N_] = a1; op[2 * N_] = a2; op[3 * N_] = a3;
}

// ---------------- devoxelize + point-branch GN/swish + add ------------------
__global__ void final_kernel(const float* __restrict__ nc, const float* __restrict__ h2,
                             const float* __restrict__ pf, const float* __restrict__ gamma,
                             const float* __restrict__ beta,
                             const float* __restrict__ mean, const float* __restrict__ rstd,
                             float* __restrict__ out) {
    int t = blockIdx.x * blockDim.x + threadIdx.x;   // over B*(COUT/4)*N
    int n = t & (N_ - 1);
    int r = t >> 12;
    int o = (r & 31) * 4;
    int b = r >> 5;

    float ncx = nc[(b * N_ + n) * 3 + 0];
    float ncy = nc[(b * N_ + n) * 3 + 1];
    float ncz = nc[(b * N_ + n) * 3 + 2];
    float fx = floorf(ncx), fy = floorf(ncy), fz = floorf(ncz);
    float dx = ncx - fx, dy = ncy - fy, dz = ncz - fz;
    int ix0 = (int)fx, iy0 = (int)fy, iz0 = (int)fz;
    int ix1 = min(ix0 + 1, R_ - 1), iy1 = min(iy0 + 1, R_ - 1), iz1 = min(iz0 + 1, R_ - 1);
    float wx[2] = {1.f - dx, dx}, wy[2] = {1.f - dy, dy}, wz[2] = {1.f - dz, dz};
    int xs[2] = {ix0, ix1}, ys[2] = {iy0, iy1}, zs[2] = {iz0, iz1};

    float d0 = 0.f, d1 = 0.f, d2 = 0.f, d3 = 0.f;
    const float* hb = &h2[(b * COUT_ + o) * R3_];
    #pragma unroll
    for (int k = 0; k < 8; k++) {
        int kx = k >> 2, ky = (k >> 1) & 1, kz = k & 1;
        float wk = wx[kx] * wy[ky] * wz[kz];
        int id = (xs[kx] * R_ + ys[ky]) * R_ + zs[kz];
        d0 += wk * hb[id];
        d1 += wk * hb[R3_ + id];
        d2 += wk * hb[2 * R3_ + id];
        d3 += wk * hb[3 * R3_ + id];
    }

    int idx = b * NG_ + (o >> 4);        // 4 consecutive ch never cross a group
    float m = mean[idx], rs = rstd[idx];
    const float* pp = &pf[(b * COUT_ + o) * N_ + n];
    float* op = &out[(b * COUT_ + o) * N_ + n];
    float dv[4] = {d0, d1, d2, d3};
    #pragma unroll
    for (int j = 0; j < 4; j++) {
        int c = o + j;
        float y = (pp[j * N_] - m) * rs * gamma[c] + beta[c];
        op[j * N_] = dv[j] + y / (1.0f + expf(-y));
    }
}

// ---------------- host launcher ----------------------------------------------
extern "C" void kernel_launch(void* const* d_in, const int* in_sizes, int n_in,
                              void* d_out, int out_size) {
    const float* features = (const float*)d_in[0];
    const float* coords   = (const float*)d_in[1];
    const float* c1w = (const float*)d_in[2];
    const float* c1b = (const float*)d_in[3];
    const float* g1g = (const float*)d_in[4];
    const float* g1b = (const float*)d_in[5];
    const float* c2w = (const float*)d_in[6];
    const float* c2b = (const float*)d_in[7];
    const float* g2g = (const float*)d_in[8];
    const float* g2b = (const float*)d_in[9];
    const float* ptw = (const float*)d_in[10];
    const float* ptb = (const float*)d_in[11];
    const float* pgg = (const float*)d_in[12];
    const float* pgb = (const float*)d_in[13];
    float* out = (float*)d_out;

    float *grid_p, *cnt_p, *h1, *h2, *pf, *nc, *mean_p, *rstd_p;
    int* vox_p;
    cudaGetSymbolAddress((void**)&grid_p, g_grid);
    cudaGetSymbolAddress((void**)&cnt_p, g_cnt);
    cudaGetSymbolAddress((void**)&vox_p, g_vox);
    cudaGetSymbolAddress((void**)&nc, g_nc);
    cudaGetSymbolAddress((void**)&h1, g_h1);
    cudaGetSymbolAddress((void**)&h2, g_h2);
    cudaGetSymbolAddress((void**)&pf, g_pf);
    cudaGetSymbolAddress((void**)&mean_p, g_mean);
    cudaGetSymbolAddress((void**)&rstd_p, g_rstd);

    zero_kernel<<<4096, 256>>>(grid_p, cnt_p);
    coords_kernel<<<B_, 256>>>(coords, nc, vox_p, cnt_p);
    scatter_kernel<<<8192, 256>>>(features, vox_p, grid_p);          // B*CIN*N
    normgrid_kernel<<<65536, 256>>>(grid_p, cnt_p);                  // B*CIN*R3

    conv3d_kernel<<<dim3(64, 8, 8), 256>>>(grid_p, c1w, c1b, h1, CIN_);
    gn_stats_kernel<<<B_ * NG_, 512>>>(h1, R3_, mean_p, rstd_p);
    gn_apply_kernel<<<131072, 256>>>(h1, g1g, g1b, mean_p, rstd_p, R3_);

    conv3d_kernel<<<dim3(64, 8, 8), 256>>>(h1, c2w, c2b, h2, COUT_);
    gn_stats_kernel<<<B_ * NG_, 512>>>(h2, R3_, mean_p, rstd_p);
    gn_apply_kernel<<<131072, 256>>>(h2, g2g, g2b, mean_p, rstd_p, R3_);

    ptgemm_kernel<<<4096, 256>>>(features, ptw, ptb, pf);            // B*(COUT/4)*N
    gn_stats_kernel<<<B_ * NG_, 512>>>(pf, N_, mean_p, rstd_p);
    final_kernel<<<4096, 256>>>(nc, h2, pf, pgg, pgb, mean_p, rstd_p, out);
}